// round 1
// baseline (speedup 1.0000x reference)
#include <cuda_runtime.h>

// Problem constants
#define BB 8
#define SS 4096
#define FF 512
#define HH 2048
#define WW 16
#define LL (SS - WW + 1)     // 4081
#define KD (WW * FF)         // 8192
#define MT (BB * LL)         // 32648

// Intermediate h activation scratch: [MT, HH] fp32 = ~267 MB static device global.
__device__ float g_h[(size_t)MT * HH];

// ---------------------------------------------------------------------------
// Kernel 1: h = relu(A @ w1 + b1)
//   A[m, k] = x[(b*SS + l)*FF + k], m = b*LL + l   (overlapping strided rows)
//   M = MT (32648), N = HH (2048), K = KD (8192)
// 128x128 tile, BK=16, 256 threads, 8x8 accumulators per thread.
// ---------------------------------------------------------------------------
__global__ __launch_bounds__(256, 2)
void k1_gemm_relu(const float* __restrict__ x,
                  const float* __restrict__ w1,
                  const float* __restrict__ b1)
{
    __shared__ float As[16][128];   // [k][m_local] (transposed A tile)
    __shared__ float Bs[16][128];   // [k][n_local]

    const int n0 = blockIdx.x * 128;
    const int m0 = blockIdx.y * 128;
    const int tid = threadIdx.x;
    const int tr = tid >> 4;        // 0..15
    const int tc = tid & 15;        // 0..15

    float acc[8][8];
#pragma unroll
    for (int i = 0; i < 8; i++)
#pragma unroll
        for (int j = 0; j < 8; j++) acc[i][j] = 0.f;

    // Precompute the A-row base pointers for the 2 rows this thread loads.
    const float* arow[2];
#pragma unroll
    for (int i = 0; i < 2; i++) {
        int id = tid + i * 256;
        int ar = id >> 2;           // 0..127
        int m = m0 + ar;
        if (m < MT) {
            int b = m / LL;
            int l = m - b * LL;
            arow[i] = x + (size_t)(b * SS + l) * FF;
        } else {
            arow[i] = nullptr;
        }
    }

    for (int k0 = 0; k0 < KD; k0 += 16) {
        // Load A tile (128 x 16) -> As transposed
#pragma unroll
        for (int i = 0; i < 2; i++) {
            int id = tid + i * 256;
            int ar = id >> 2;
            int ac = (id & 3) * 4;
            float4 v = make_float4(0.f, 0.f, 0.f, 0.f);
            if (arow[i]) v = *reinterpret_cast<const float4*>(arow[i] + k0 + ac);
            As[ac + 0][ar] = v.x;
            As[ac + 1][ar] = v.y;
            As[ac + 2][ar] = v.z;
            As[ac + 3][ar] = v.w;
        }
        // Load B tile (16 x 128) from w1
#pragma unroll
        for (int i = 0; i < 2; i++) {
            int id = tid + i * 256;
            int br = id >> 5;            // 0..15
            int bc = (id & 31) * 4;      // 0..124
            float4 v = *reinterpret_cast<const float4*>(
                w1 + (size_t)(k0 + br) * HH + n0 + bc);
            *reinterpret_cast<float4*>(&Bs[br][bc]) = v;
        }
        __syncthreads();

#pragma unroll
        for (int kk = 0; kk < 16; kk++) {
            float a[8], b[8];
#pragma unroll
            for (int i = 0; i < 8; i++) a[i] = As[kk][tr * 8 + i];
#pragma unroll
            for (int j = 0; j < 8; j++) b[j] = Bs[kk][tc * 8 + j];
#pragma unroll
            for (int i = 0; i < 8; i++)
#pragma unroll
                for (int j = 0; j < 8; j++)
                    acc[i][j] = fmaf(a[i], b[j], acc[i][j]);
        }
        __syncthreads();
    }

    // Epilogue: relu(acc + b1) -> g_h
    float bias[8];
#pragma unroll
    for (int j = 0; j < 8; j++) bias[j] = b1[n0 + tc * 8 + j];

#pragma unroll
    for (int i = 0; i < 8; i++) {
        int m = m0 + tr * 8 + i;
        if (m >= MT) continue;
        float* hrow = g_h + (size_t)m * HH + n0 + tc * 8;
#pragma unroll
        for (int j = 0; j < 8; j += 4) {
            float4 v;
            v.x = fmaxf(acc[i][j + 0] + bias[j + 0], 0.f);
            v.y = fmaxf(acc[i][j + 1] + bias[j + 1], 0.f);
            v.z = fmaxf(acc[i][j + 2] + bias[j + 2], 0.f);
            v.w = fmaxf(acc[i][j + 3] + bias[j + 3], 0.f);
            *reinterpret_cast<float4*>(hrow + j) = v;
        }
    }
}

// ---------------------------------------------------------------------------
// Kernel 2: y = h @ w2 + b2
//   M = MT, N = FF (512), K = HH (2048). Writes to out[(b*SS + l)*FF + n].
// ---------------------------------------------------------------------------
__global__ __launch_bounds__(256, 2)
void k2_gemm_bias(const float* __restrict__ w2,
                  const float* __restrict__ b2,
                  float* __restrict__ out)
{
    __shared__ float As[16][128];
    __shared__ float Bs[16][128];

    const int n0 = blockIdx.x * 128;
    const int m0 = blockIdx.y * 128;
    const int tid = threadIdx.x;
    const int tr = tid >> 4;
    const int tc = tid & 15;

    float acc[8][8];
#pragma unroll
    for (int i = 0; i < 8; i++)
#pragma unroll
        for (int j = 0; j < 8; j++) acc[i][j] = 0.f;

    for (int k0 = 0; k0 < HH; k0 += 16) {
        // Load A tile from g_h (contiguous rows of width HH)
#pragma unroll
        for (int i = 0; i < 2; i++) {
            int id = tid + i * 256;
            int ar = id >> 2;
            int ac = (id & 3) * 4;
            int m = m0 + ar;
            float4 v = make_float4(0.f, 0.f, 0.f, 0.f);
            if (m < MT)
                v = *reinterpret_cast<const float4*>(g_h + (size_t)m * HH + k0 + ac);
            As[ac + 0][ar] = v.x;
            As[ac + 1][ar] = v.y;
            As[ac + 2][ar] = v.z;
            As[ac + 3][ar] = v.w;
        }
        // Load B tile from w2 (rows of width FF=512)
#pragma unroll
        for (int i = 0; i < 2; i++) {
            int id = tid + i * 256;
            int br = id >> 5;
            int bc = (id & 31) * 4;
            float4 v = *reinterpret_cast<const float4*>(
                w2 + (size_t)(k0 + br) * FF + n0 + bc);
            *reinterpret_cast<float4*>(&Bs[br][bc]) = v;
        }
        __syncthreads();

#pragma unroll
        for (int kk = 0; kk < 16; kk++) {
            float a[8], b[8];
#pragma unroll
            for (int i = 0; i < 8; i++) a[i] = As[kk][tr * 8 + i];
#pragma unroll
            for (int j = 0; j < 8; j++) b[j] = Bs[kk][tc * 8 + j];
#pragma unroll
            for (int i = 0; i < 8; i++)
#pragma unroll
                for (int j = 0; j < 8; j++)
                    acc[i][j] = fmaf(a[i], b[j], acc[i][j]);
        }
        __syncthreads();
    }

    float bias[8];
#pragma unroll
    for (int j = 0; j < 8; j++) bias[j] = b2[n0 + tc * 8 + j];

#pragma unroll
    for (int i = 0; i < 8; i++) {
        int m = m0 + tr * 8 + i;
        if (m >= MT) continue;
        int b = m / LL;
        int l = m - b * LL;
        float* yrow = out + (size_t)(b * SS + l) * FF + n0 + tc * 8;
#pragma unroll
        for (int j = 0; j < 8; j += 4) {
            float4 v;
            v.x = acc[i][j + 0] + bias[j + 0];
            v.y = acc[i][j + 1] + bias[j + 1];
            v.z = acc[i][j + 2] + bias[j + 2];
            v.w = acc[i][j + 3] + bias[j + 3];
            *reinterpret_cast<float4*>(yrow + j) = v;
        }
    }
}

// ---------------------------------------------------------------------------
// Kernel 3: zero the (W-1) trailing pad rows per batch.
// ---------------------------------------------------------------------------
__global__ void k3_pad(float* __restrict__ out)
{
    int idx = blockIdx.x * blockDim.x + threadIdx.x;
    const int total = BB * (WW - 1) * FF;
    if (idx >= total) return;
    int f = idx % FF;
    int t = idx / FF;
    int l = LL + (t % (WW - 1));
    int b = t / (WW - 1);
    out[(size_t)(b * SS + l) * FF + f] = 0.f;
}

extern "C" void kernel_launch(void* const* d_in, const int* in_sizes, int n_in,
                              void* d_out, int out_size)
{
    const float* x  = (const float*)d_in[0];
    const float* w1 = (const float*)d_in[1];
    const float* b1 = (const float*)d_in[2];
    const float* w2 = (const float*)d_in[3];
    const float* b2 = (const float*)d_in[4];
    float* out = (float*)d_out;

    dim3 g1(HH / 128, (MT + 127) / 128);   // (16, 256)
    k1_gemm_relu<<<g1, 256>>>(x, w1, b1);

    dim3 g2(FF / 128, (MT + 127) / 128);   // (4, 256)
    k2_gemm_bias<<<g2, 256>>>(w2, b2, out);

    int pad_total = BB * (WW - 1) * FF;
    k3_pad<<<(pad_total + 255) / 256, 256>>>(out);
}